// round 14
// baseline (speedup 1.0000x reference)
#include <cuda_runtime.h>
#include <math.h>

// CSCR fused pipeline, B=32, C=256, H=W=56 (HW=3136), sm_103a. 3 launches:
// k_sa:    partial channel reduce (C split x8, 1792 blocks) + last-z-block
//          per (x,b) tile combines its own 128 pixels -> sigmoid(sa).
//          Resets g_n.                             [reads 205.5 MB streaming]
// k_stats: 8-ch blocks dot(sa,x), ||x||^2 + last-block-per-(b,s) stable
//          rank argsort + atomicMax positive count [reads 205.5 MB streaming]
// k_out:   4-ch/thread inline srcmap gather * sa   [reads 205.5, writes 205.5 MB]
//
// Last-block ordering: stores -> __threadfence() -> __syncthreads() ->
// tid0 atomicAdd (the barrier after the fence is required: the fence only
// orders the executing thread's own stores).

#define NB  32
#define NC  256
#define NHW 3136
#define NG4 784            // NHW/4
#define NZ  8              // C-chunks in k_sa
#define CPZ 32             // channels per chunk
#define NX  7              // x-chunks of 128 float4 groups
#define EPSF 1e-12f

__device__ __align__(16) float  g_sa[NB * NHW];        // sigmoid(sa)
__device__ __align__(16) float4 g_ps [NZ * NB * NG4];  // partial sum (rgb+ir combined)
__device__ __align__(16) float4 g_pmr[NZ * NB * NG4];  // partial max rgb
__device__ __align__(16) float4 g_pmi[NZ * NB * NG4];  // partial max ir
__device__ float g_dot[2][NB * NC];
__device__ float g_nsq[2][NB * NC];
__device__ int   g_ord[2][NB * NC];
__device__ int   g_n[2];
__device__ int   g_done_sa[NB * NX];     // zero-init; every use self-resets
__device__ int   g_done_st[2 * NB];      // zero-init; every use self-resets

// ---------------------------------------------------------------------------
// Pass 1: partial per-pixel channel reductions (32-ch chunk, streaming loads).
// The LAST of the NZ z-blocks sharing an (x,b) tile combines the 8 partials
// for ITS OWN 128 pixels -> sigmoid(sa). 224 tiny tails, fully overlapped.
// ---------------------------------------------------------------------------
__global__ void __launch_bounds__(128) k_sa(const float* __restrict__ rgb,
                                            const float* __restrict__ ir) {
    int tid = threadIdx.x;
    int x = blockIdx.x, b = blockIdx.y, z = blockIdx.z;
    int gx = x * 128 + tid;
    bool act = (gx < NG4);

    if (x == 0 && b == 0 && z == 0 && tid < 2) g_n[tid] = 0;

    if (act) {
        const float4* r4 = (const float4*)(rgb + (size_t)b * NC * NHW) + (size_t)z * CPZ * NG4;
        const float4* i4 = (const float4*)(ir  + (size_t)b * NC * NHW) + (size_t)z * CPZ * NG4;

        float4 s  = make_float4(0.f, 0.f, 0.f, 0.f);
        float4 mr = make_float4(-3.402823466e38f, -3.402823466e38f, -3.402823466e38f, -3.402823466e38f);
        float4 mi = mr;

        #pragma unroll 8
        for (int c = 0; c < CPZ; c++) {
            float4 a = __ldcs(r4 + c * NG4 + gx);
            float4 d = __ldcs(i4 + c * NG4 + gx);
            s.x += a.x + d.x; s.y += a.y + d.y; s.z += a.z + d.z; s.w += a.w + d.w;
            mr.x = fmaxf(mr.x, a.x); mr.y = fmaxf(mr.y, a.y);
            mr.z = fmaxf(mr.z, a.z); mr.w = fmaxf(mr.w, a.w);
            mi.x = fmaxf(mi.x, d.x); mi.y = fmaxf(mi.y, d.y);
            mi.z = fmaxf(mi.z, d.z); mi.w = fmaxf(mi.w, d.w);
        }
        size_t o = ((size_t)z * NB + b) * NG4 + gx;
        g_ps[o] = s; g_pmr[o] = mr; g_pmi[o] = mi;
    }

    __threadfence();        // order THIS thread's partial stores device-wide
    __syncthreads();        // ensure ALL threads' fences executed
    __shared__ int s_last;
    if (tid == 0) {
        int old = atomicAdd(&g_done_sa[b * NX + x], 1);
        int last = (old == NZ - 1);
        if (last) g_done_sa[b * NX + x] = 0;      // self-reset for graph replay
        s_last = last;
    }
    __syncthreads();
    if (!s_last || !act) return;

    // Tile combine tail: this thread finishes sa for its own pixel group gx.
    float4 s  = make_float4(0.f, 0.f, 0.f, 0.f);
    float4 mr = make_float4(-3.402823466e38f, -3.402823466e38f, -3.402823466e38f, -3.402823466e38f);
    float4 mi = mr;
    #pragma unroll
    for (int zz = 0; zz < NZ; zz++) {
        size_t o = ((size_t)zz * NB + b) * NG4 + gx;
        float4 ps = __ldcg(&g_ps[o]);
        float4 pr = __ldcg(&g_pmr[o]);
        float4 pi = __ldcg(&g_pmi[o]);
        s.x += ps.x; s.y += ps.y; s.z += ps.z; s.w += ps.w;
        mr.x = fmaxf(mr.x, pr.x); mr.y = fmaxf(mr.y, pr.y);
        mr.z = fmaxf(mr.z, pr.z); mr.w = fmaxf(mr.w, pr.w);
        mi.x = fmaxf(mi.x, pi.x); mi.y = fmaxf(mi.y, pi.y);
        mi.z = fmaxf(mi.z, pi.z); mi.w = fmaxf(mi.w, pi.w);
    }
    const float invC = 1.0f / (float)NC;
    float4 o4;
    float sa;
    sa = fmaxf(s.x * invC, mr.x + mi.x); o4.x = 1.0f / (1.0f + expf(-sa));
    sa = fmaxf(s.y * invC, mr.y + mi.y); o4.y = 1.0f / (1.0f + expf(-sa));
    sa = fmaxf(s.z * invC, mr.z + mi.z); o4.z = 1.0f / (1.0f + expf(-sa));
    sa = fmaxf(s.w * invC, mr.w + mi.w); o4.w = 1.0f / (1.0f + expf(-sa));
    ((float4*)(g_sa + (size_t)b * NHW))[gx] = o4;
}

// ---------------------------------------------------------------------------
// Pass 2: 8 channels per block — one sa load feeds 8 dot accumulations.
// LAST block per (b,s) runs the stable rank argsort inline (key = dot/nx;
// common positive factor ||sa|| dropped — identical order and sign) and
// atomicMax's the positive count into g_n[s].
// ---------------------------------------------------------------------------
__global__ void __launch_bounds__(128) k_stats(const float* __restrict__ rgb,
                                               const float* __restrict__ ir) {
    int c0 = blockIdx.x * 8, b = blockIdx.y, s = blockIdx.z;
    int tid = threadIdx.x;

    const float4* x4  = (const float4*)((s == 0 ? rgb : ir) + ((size_t)b * NC + c0) * NHW);
    const float4* sa4 = (const float4*)(g_sa + (size_t)b * NHW);

    float d[8], n[8];
    #pragma unroll
    for (int k = 0; k < 8; k++) { d[k] = 0.f; n[k] = 0.f; }

    for (int g = tid; g < NG4; g += 128) {
        float4 a = sa4[g];
        #pragma unroll
        for (int k = 0; k < 8; k++) {
            float4 v = __ldcs(x4 + k * NG4 + g);
            d[k] += v.x * a.x + v.y * a.y + v.z * a.z + v.w * a.w;
            n[k] += v.x * v.x + v.y * v.y + v.z * v.z + v.w * v.w;
        }
    }
    #pragma unroll
    for (int o = 16; o > 0; o >>= 1) {
        #pragma unroll
        for (int k = 0; k < 8; k++) {
            d[k] += __shfl_down_sync(0xffffffffu, d[k], o);
            n[k] += __shfl_down_sync(0xffffffffu, n[k], o);
        }
    }
    __shared__ float sd[4][8], sn[4][8];   // [warp][channel]
    if ((tid & 31) == 0) {
        int w = tid >> 5;
        #pragma unroll
        for (int k = 0; k < 8; k++) { sd[w][k] = d[k]; sn[w][k] = n[k]; }
    }
    __syncthreads();
    if (tid < 8) {
        float dd = (sd[0][tid] + sd[1][tid]) + (sd[2][tid] + sd[3][tid]);
        float nn = (sn[0][tid] + sn[1][tid]) + (sn[2][tid] + sn[3][tid]);
        g_dot[s][b * NC + c0 + tid] = dd;
        g_nsq[s][b * NC + c0 + tid] = nn;
    }

    __threadfence();        // order this thread's g_dot/g_nsq stores
    __syncthreads();        // all fences done before counter bump
    __shared__ int s_last;
    if (tid == 0) {
        int old = atomicAdd(&g_done_st[s * NB + b], 1);
        int last = (old == NC / 8 - 1);
        if (last) g_done_st[s * NB + b] = 0;      // self-reset for graph replay
        s_last = last;
    }
    __syncthreads();
    if (!s_last) return;

    // Sort tail: 128 threads, 2 channels each (c = tid, tid+128).
    __shared__ __align__(16) float s_key[NC];
    float nx0  = fmaxf(sqrtf(__ldcg(&g_nsq[s][b * NC + tid])), EPSF);
    float sim0 = __ldcg(&g_dot[s][b * NC + tid]) / nx0;
    float nx1  = fmaxf(sqrtf(__ldcg(&g_nsq[s][b * NC + tid + 128])), EPSF);
    float sim1 = __ldcg(&g_dot[s][b * NC + tid + 128]) / nx1;
    s_key[tid] = sim0;
    s_key[tid + 128] = sim1;

    int c1 = __syncthreads_count(sim0 > 0.f);     // barriers also publish s_key
    int c2 = __syncthreads_count(sim1 > 0.f);
    if (tid == 0) atomicMax(&g_n[s], c1 + c2);    // batch max (reset in k_sa)

    // stable rank: # keys strictly less, plus equal keys with smaller index
    const float4* k4 = (const float4*)s_key;
    int r0 = 0, r1 = 0;
    int t1 = tid + 128;
    #pragma unroll 8
    for (int j4 = 0; j4 < NC / 4; j4++) {
        float4 k = k4[j4];                        // broadcast LDS.128
        int j = j4 * 4;
        r0 += (k.x < sim0) || (k.x == sim0 && j     < tid);
        r0 += (k.y < sim0) || (k.y == sim0 && j + 1 < tid);
        r0 += (k.z < sim0) || (k.z == sim0 && j + 2 < tid);
        r0 += (k.w < sim0) || (k.w == sim0 && j + 3 < tid);
        r1 += (k.x < sim1) || (k.x == sim1 && j     < t1);
        r1 += (k.y < sim1) || (k.y == sim1 && j + 1 < t1);
        r1 += (k.z < sim1) || (k.z == sim1 && j + 2 < t1);
        r1 += (k.w < sim1) || (k.w == sim1 && j + 3 < t1);
    }
    g_ord[s][b * NC + r0] = tid;
    g_ord[s][b * NC + r1] = t1;
}

// ---------------------------------------------------------------------------
// Pass 3: out = (src>=0 ? x[src] : max(rgb[lo0], ir[lo1])) * sa_sig.
// 4 channels per thread; srcmap derived inline from g_ord + g_n.
// ---------------------------------------------------------------------------
__device__ __forceinline__ int src_of(const int* __restrict__ ord, int c,
                                      int n_self, int n_other) {
    if (n_other > n_self && n_self < NC) {
        if (c < n_self)  return __ldg(ord + c);
        if (c == n_self) return -1;               // extra_fea slot
        return __ldg(ord + c - 1);
    }
    return __ldg(ord + c);
}

__global__ void __launch_bounds__(256) k_out(const float* __restrict__ rgb,
                                             const float* __restrict__ ir,
                                             float* __restrict__ out) {
    int idx = blockIdx.x * blockDim.x + threadIdx.x;     // [0, NB*64*NG4)
    int g  = idx % NG4;
    int t  = idx / NG4;
    int cp = t & 63;
    int b  = t >> 6;
    int c0 = cp * 4;

    float4 a = __ldg((const float4*)(g_sa + (size_t)b * NHW) + g);

    const float4* rb = (const float4*)(rgb + (size_t)b * NC * NHW);
    const float4* ib = (const float4*)(ir  + (size_t)b * NC * NHW);

    int n0 = __ldg(&g_n[0]);
    int n1 = __ldg(&g_n[1]);
    const int* ord0 = g_ord[0] + b * NC;
    const int* ord1 = g_ord[1] + b * NC;

    int sr[4], si[4];
    #pragma unroll
    for (int k = 0; k < 4; k++) {
        sr[k] = src_of(ord0, c0 + k, n0, n1);
        si[k] = src_of(ord1, c0 + k, n1, n0);
    }

    float4 ex;  // extra_fea = max(lowest-sim rgb, lowest-sim ir); lazy
    bool need_ex = false;
    #pragma unroll
    for (int k = 0; k < 4; k++) need_ex |= (sr[k] < 0) | (si[k] < 0);
    if (need_ex) {
        float4 p = __ldcs(rb + (size_t)__ldg(ord0) * NG4 + g);
        float4 q = __ldcs(ib + (size_t)__ldg(ord1) * NG4 + g);
        ex = make_float4(fmaxf(p.x, q.x), fmaxf(p.y, q.y), fmaxf(p.z, q.z), fmaxf(p.w, q.w));
    }

    float4 vr[4], vi[4];
    #pragma unroll
    for (int k = 0; k < 4; k++)
        vr[k] = (sr[k] >= 0) ? __ldcs(rb + (size_t)sr[k] * NG4 + g) : ex;
    #pragma unroll
    for (int k = 0; k < 4; k++)
        vi[k] = (si[k] >= 0) ? __ldcs(ib + (size_t)si[k] * NG4 + g) : ex;

    size_t base_r = ((size_t)b * NC + c0) * NG4 + g;
    size_t base_i = (size_t)NB * NC * NG4 + base_r;

    #pragma unroll
    for (int k = 0; k < 4; k++)
        __stcs((float4*)out + base_r + (size_t)k * NG4,
               make_float4(vr[k].x * a.x, vr[k].y * a.y, vr[k].z * a.z, vr[k].w * a.w));
    #pragma unroll
    for (int k = 0; k < 4; k++)
        __stcs((float4*)out + base_i + (size_t)k * NG4,
               make_float4(vi[k].x * a.x, vi[k].y * a.y, vi[k].z * a.z, vi[k].w * a.w));
}

extern "C" void kernel_launch(void* const* d_in, const int* in_sizes, int n_in,
                              void* d_out, int out_size) {
    (void)in_sizes; (void)n_in; (void)out_size;
    const float* rgb = (const float*)d_in[0];
    const float* ir  = (const float*)d_in[1];
    float* out = (float*)d_out;

    k_sa<<<dim3(NX, NB, NZ), 128>>>(rgb, ir);
    k_stats<<<dim3(NC / 8, NB, 2), 128>>>(rgb, ir);
    k_out<<<(NB * 64 * NG4) / 256, 256>>>(rgb, ir, out);
}

// round 15
// speedup vs baseline: 1.0726x; 1.0726x over previous
#include <cuda_runtime.h>
#include <math.h>

// CSCR fused pipeline, B=32, C=256, H=W=56 (HW=3136), sm_103a.
// Proven R11 5-launch structure (142.1 us) + k_sa1 unroll 16.
// k_sa1: partial channel reduce (C split x8) + g_n reset  [reads 205.5 MB, streaming]
// k_sa2: combine partials -> sigmoid(sa)                   [reads 9.6 MB, L2-resident]
// k_stats: 8-ch blocks: dot(sa,x), ||x||^2                 [reads 205.5 MB, streaming]
// k_sort: key = dot/nx, positive counts -> atomicMax(g_n), stable rank argsort
// k_out: 4-ch/thread inline srcmap gather * sa             [reads 205.5, writes 205.5 MB]

#define NB  32
#define NC  256
#define NHW 3136
#define NG4 784            // NHW/4
#define NZ  8              // C-chunks in k_sa1
#define CPZ 32             // channels per chunk
#define EPSF 1e-12f

__device__ __align__(16) float  g_sa[NB * NHW];        // sigmoid(sa)
__device__ __align__(16) float4 g_ps [NZ * NB * NG4];  // partial sum (rgb+ir combined)
__device__ __align__(16) float4 g_pmr[NZ * NB * NG4];  // partial max rgb
__device__ __align__(16) float4 g_pmi[NZ * NB * NG4];  // partial max ir
__device__ float g_dot[2][NB * NC];
__device__ float g_nsq[2][NB * NC];
__device__ int   g_ord[2][NB * NC];
__device__ int   g_n[2];

// ---------------------------------------------------------------------------
// Pass 1a: partial per-pixel channel reductions over a 32-channel chunk.
// grid (7, B, 8) x 128. Streaming loads; deep unroll for MLP. Block (0,0,0)
// resets g_n (consumed only by later kernels).
// ---------------------------------------------------------------------------
__global__ void __launch_bounds__(128) k_sa1(const float* __restrict__ rgb,
                                             const float* __restrict__ ir) {
    if (blockIdx.x == 0 && blockIdx.y == 0 && blockIdx.z == 0 && threadIdx.x < 2)
        g_n[threadIdx.x] = 0;

    int g = blockIdx.x * blockDim.x + threadIdx.x;
    if (g >= NG4) return;
    int b = blockIdx.y, z = blockIdx.z;

    const float4* r4 = (const float4*)(rgb + (size_t)b * NC * NHW) + (size_t)z * CPZ * NG4;
    const float4* i4 = (const float4*)(ir  + (size_t)b * NC * NHW) + (size_t)z * CPZ * NG4;

    float4 s  = make_float4(0.f, 0.f, 0.f, 0.f);
    float4 mr = make_float4(-3.402823466e38f, -3.402823466e38f, -3.402823466e38f, -3.402823466e38f);
    float4 mi = mr;

    #pragma unroll 16
    for (int c = 0; c < CPZ; c++) {
        float4 a = __ldcs(r4 + c * NG4 + g);
        float4 d = __ldcs(i4 + c * NG4 + g);
        s.x += a.x + d.x; s.y += a.y + d.y; s.z += a.z + d.z; s.w += a.w + d.w;
        mr.x = fmaxf(mr.x, a.x); mr.y = fmaxf(mr.y, a.y);
        mr.z = fmaxf(mr.z, a.z); mr.w = fmaxf(mr.w, a.w);
        mi.x = fmaxf(mi.x, d.x); mi.y = fmaxf(mi.y, d.y);
        mi.z = fmaxf(mi.z, d.z); mi.w = fmaxf(mi.w, d.w);
    }
    size_t o = ((size_t)z * NB + b) * NG4 + g;
    g_ps[o] = s; g_pmr[o] = mr; g_pmi[o] = mi;   // default policy: L2-resident
}

// ---------------------------------------------------------------------------
// Pass 1b: combine 8 partials -> sa = max(mean, max_r + max_i) -> sigmoid.
// ---------------------------------------------------------------------------
__global__ void __launch_bounds__(128) k_sa2() {
    int g = blockIdx.x * blockDim.x + threadIdx.x;
    if (g >= NG4) return;
    int b = blockIdx.y;

    float4 s  = make_float4(0.f, 0.f, 0.f, 0.f);
    float4 mr = make_float4(-3.402823466e38f, -3.402823466e38f, -3.402823466e38f, -3.402823466e38f);
    float4 mi = mr;

    #pragma unroll
    for (int z = 0; z < NZ; z++) {
        size_t o = ((size_t)z * NB + b) * NG4 + g;
        float4 ps = g_ps[o], pr = g_pmr[o], pi = g_pmi[o];
        s.x += ps.x; s.y += ps.y; s.z += ps.z; s.w += ps.w;
        mr.x = fmaxf(mr.x, pr.x); mr.y = fmaxf(mr.y, pr.y);
        mr.z = fmaxf(mr.z, pr.z); mr.w = fmaxf(mr.w, pr.w);
        mi.x = fmaxf(mi.x, pi.x); mi.y = fmaxf(mi.y, pi.y);
        mi.z = fmaxf(mi.z, pi.z); mi.w = fmaxf(mi.w, pi.w);
    }
    const float invC = 1.0f / (float)NC;
    float4 o4;
    float sa;
    sa = fmaxf(s.x * invC, mr.x + mi.x); o4.x = 1.0f / (1.0f + expf(-sa));
    sa = fmaxf(s.y * invC, mr.y + mi.y); o4.y = 1.0f / (1.0f + expf(-sa));
    sa = fmaxf(s.z * invC, mr.z + mi.z); o4.z = 1.0f / (1.0f + expf(-sa));
    sa = fmaxf(s.w * invC, mr.w + mi.w); o4.w = 1.0f / (1.0f + expf(-sa));
    ((float4*)(g_sa + (size_t)b * NHW))[g] = o4;
}

// ---------------------------------------------------------------------------
// Pass 2: 8 channels per block — one sa load feeds 8 dot accumulations
// (sa L2 traffic /8); 8 independent streaming loads per iteration for MLP.
// ---------------------------------------------------------------------------
__global__ void __launch_bounds__(128) k_stats(const float* __restrict__ rgb,
                                               const float* __restrict__ ir) {
    int c0 = blockIdx.x * 8, b = blockIdx.y, s = blockIdx.z;
    int tid = threadIdx.x;

    const float4* x4  = (const float4*)((s == 0 ? rgb : ir) + ((size_t)b * NC + c0) * NHW);
    const float4* sa4 = (const float4*)(g_sa + (size_t)b * NHW);

    float d[8], n[8];
    #pragma unroll
    for (int k = 0; k < 8; k++) { d[k] = 0.f; n[k] = 0.f; }

    for (int g = tid; g < NG4; g += 128) {
        float4 a = sa4[g];
        #pragma unroll
        for (int k = 0; k < 8; k++) {
            float4 v = __ldcs(x4 + k * NG4 + g);
            d[k] += v.x * a.x + v.y * a.y + v.z * a.z + v.w * a.w;
            n[k] += v.x * v.x + v.y * v.y + v.z * v.z + v.w * v.w;
        }
    }
    #pragma unroll
    for (int o = 16; o > 0; o >>= 1) {
        #pragma unroll
        for (int k = 0; k < 8; k++) {
            d[k] += __shfl_down_sync(0xffffffffu, d[k], o);
            n[k] += __shfl_down_sync(0xffffffffu, n[k], o);
        }
    }
    __shared__ float sd[4][8], sn[4][8];   // [warp][channel]
    if ((tid & 31) == 0) {
        int w = tid >> 5;
        #pragma unroll
        for (int k = 0; k < 8; k++) { sd[w][k] = d[k]; sn[w][k] = n[k]; }
    }
    __syncthreads();
    if (tid < 8) {
        float dd = (sd[0][tid] + sd[1][tid]) + (sd[2][tid] + sd[3][tid]);
        float nn = (sn[0][tid] + sn[1][tid]) + (sn[2][tid] + sn[3][tid]);
        g_dot[s][b * NC + c0 + tid] = dd;
        g_nsq[s][b * NC + c0 + tid] = nn;
    }
}

// ---------------------------------------------------------------------------
// Pass 3: ordering key = dot / nx (common positive factor ||sa|| dropped:
// identical argsort order and sign). Positive count -> atomicMax(g_n[s]);
// stable rank argsort via broadcast LDS.128 loop.
// ---------------------------------------------------------------------------
__global__ void __launch_bounds__(256) k_sort() {
    int b = blockIdx.x, s = blockIdx.y;
    int tid = threadIdx.x;  // 256 == NC

    __shared__ __align__(16) float s_key[NC];

    float nx  = fmaxf(sqrtf(g_nsq[s][b * NC + tid]), EPSF);
    float sim = g_dot[s][b * NC + tid] / nx;
    s_key[tid] = sim;

    int cnt = __syncthreads_count(sim > 0.f);   // barrier also publishes s_key
    if (tid == 0) atomicMax(&g_n[s], cnt);      // batch max (reset in k_sa1)

    // stable rank: # keys strictly less, plus equal keys with smaller index
    const float4* k4 = (const float4*)s_key;
    int rank = 0;
    #pragma unroll 8
    for (int j4 = 0; j4 < NC / 4; j4++) {
        float4 k = k4[j4];                       // broadcast LDS.128
        int j = j4 * 4;
        rank += (k.x < sim) || (k.x == sim && j     < tid);
        rank += (k.y < sim) || (k.y == sim && j + 1 < tid);
        rank += (k.z < sim) || (k.z == sim && j + 2 < tid);
        rank += (k.w < sim) || (k.w == sim && j + 3 < tid);
    }
    g_ord[s][b * NC + rank] = tid;               // channel tid sits at position rank
}

// ---------------------------------------------------------------------------
// Pass 4: out = (src>=0 ? x[src] : max(rgb[lo0], ir[lo1])) * sa_sig.
// 4 channels per thread (same b,g): one sa load + one metadata set feeds
// 8 gathers/8 stores. srcmap derived inline from g_ord + g_n. Warp-uniform
// channel indices keep every gather coalesced.
// ---------------------------------------------------------------------------
__device__ __forceinline__ int src_of(const int* __restrict__ ord, int c,
                                      int n_self, int n_other) {
    if (n_other > n_self && n_self < NC) {
        if (c < n_self)  return __ldg(ord + c);
        if (c == n_self) return -1;              // extra_fea slot
        return __ldg(ord + c - 1);
    }
    return __ldg(ord + c);
}

__global__ void __launch_bounds__(256) k_out(const float* __restrict__ rgb,
                                             const float* __restrict__ ir,
                                             float* __restrict__ out) {
    int idx = blockIdx.x * blockDim.x + threadIdx.x;     // [0, NB*64*NG4)
    int g  = idx % NG4;
    int t  = idx / NG4;
    int cp = t & 63;
    int b  = t >> 6;
    int c0 = cp * 4;

    float4 a = __ldg((const float4*)(g_sa + (size_t)b * NHW) + g);

    const float4* rb = (const float4*)(rgb + (size_t)b * NC * NHW);
    const float4* ib = (const float4*)(ir  + (size_t)b * NC * NHW);

    int n0 = __ldg(&g_n[0]);
    int n1 = __ldg(&g_n[1]);
    const int* ord0 = g_ord[0] + b * NC;
    const int* ord1 = g_ord[1] + b * NC;

    int sr[4], si[4];
    #pragma unroll
    for (int k = 0; k < 4; k++) {
        sr[k] = src_of(ord0, c0 + k, n0, n1);
        si[k] = src_of(ord1, c0 + k, n1, n0);
    }

    float4 ex;  // extra_fea = max(lowest-sim rgb, lowest-sim ir); lazy
    bool need_ex = false;
    #pragma unroll
    for (int k = 0; k < 4; k++) need_ex |= (sr[k] < 0) | (si[k] < 0);
    if (need_ex) {
        float4 p = __ldcs(rb + (size_t)__ldg(ord0) * NG4 + g);
        float4 q = __ldcs(ib + (size_t)__ldg(ord1) * NG4 + g);
        ex = make_float4(fmaxf(p.x, q.x), fmaxf(p.y, q.y), fmaxf(p.z, q.z), fmaxf(p.w, q.w));
    }

    float4 vr[4], vi[4];
    #pragma unroll
    for (int k = 0; k < 4; k++)
        vr[k] = (sr[k] >= 0) ? __ldcs(rb + (size_t)sr[k] * NG4 + g) : ex;
    #pragma unroll
    for (int k = 0; k < 4; k++)
        vi[k] = (si[k] >= 0) ? __ldcs(ib + (size_t)si[k] * NG4 + g) : ex;

    size_t base_r = ((size_t)b * NC + c0) * NG4 + g;
    size_t base_i = (size_t)NB * NC * NG4 + base_r;

    #pragma unroll
    for (int k = 0; k < 4; k++)
        __stcs((float4*)out + base_r + (size_t)k * NG4,
               make_float4(vr[k].x * a.x, vr[k].y * a.y, vr[k].z * a.z, vr[k].w * a.w));
    #pragma unroll
    for (int k = 0; k < 4; k++)
        __stcs((float4*)out + base_i + (size_t)k * NG4,
               make_float4(vi[k].x * a.x, vi[k].y * a.y, vi[k].z * a.z, vi[k].w * a.w));
}

extern "C" void kernel_launch(void* const* d_in, const int* in_sizes, int n_in,
                              void* d_out, int out_size) {
    (void)in_sizes; (void)n_in; (void)out_size;
    const float* rgb = (const float*)d_in[0];
    const float* ir  = (const float*)d_in[1];
    float* out = (float*)d_out;

    k_sa1<<<dim3(7, NB, NZ), 128>>>(rgb, ir);
    k_sa2<<<dim3(7, NB), 128>>>();
    k_stats<<<dim3(NC / 8, NB, 2), 128>>>(rgb, ir);
    k_sort<<<dim3(NB, 2), 256>>>();
    k_out<<<(NB * 64 * NG4) / 256, 256>>>(rgb, ir, out);
}

// round 16
// speedup vs baseline: 1.1629x; 1.0841x over previous
#include <cuda_runtime.h>
#include <math.h>

// CSCR fused pipeline, B=32, C=256, H=W=56 (HW=3136), sm_103a.
// Proven R11 5-launch structure (measured 142.1 us, rel_err 3.4e-9).
// k_sa1: partial channel reduce (C split x8) + g_n reset  [reads 205.5 MB, streaming]
// k_sa2: combine partials -> sigmoid(sa)                   [reads 9.6 MB, L2-resident]
// k_stats: 8-ch blocks: dot(sa,x), ||x||^2                 [reads 205.5 MB, streaming]
// k_sort: key = dot/nx, positive counts -> atomicMax(g_n), stable rank argsort
// k_out: 4-ch/thread inline srcmap gather * sa             [reads 205.5, writes 205.5 MB]

#define NB  32
#define NC  256
#define NHW 3136
#define NG4 784            // NHW/4
#define NZ  8              // C-chunks in k_sa1
#define CPZ 32             // channels per chunk
#define EPSF 1e-12f

__device__ __align__(16) float  g_sa[NB * NHW];        // sigmoid(sa)
__device__ __align__(16) float4 g_ps [NZ * NB * NG4];  // partial sum (rgb+ir combined)
__device__ __align__(16) float4 g_pmr[NZ * NB * NG4];  // partial max rgb
__device__ __align__(16) float4 g_pmi[NZ * NB * NG4];  // partial max ir
__device__ float g_dot[2][NB * NC];
__device__ float g_nsq[2][NB * NC];
__device__ int   g_ord[2][NB * NC];
__device__ int   g_n[2];

// ---------------------------------------------------------------------------
// Pass 1a: partial per-pixel channel reductions over a 32-channel chunk.
// grid (7, B, 8) x 128. Streaming loads. Block (0,0,0) also resets g_n
// (read only by k_sort's atomicMax / k_out, both in later kernels).
// ---------------------------------------------------------------------------
__global__ void __launch_bounds__(128) k_sa1(const float* __restrict__ rgb,
                                             const float* __restrict__ ir) {
    if (blockIdx.x == 0 && blockIdx.y == 0 && blockIdx.z == 0 && threadIdx.x < 2)
        g_n[threadIdx.x] = 0;

    int g = blockIdx.x * blockDim.x + threadIdx.x;
    if (g >= NG4) return;
    int b = blockIdx.y, z = blockIdx.z;

    const float4* r4 = (const float4*)(rgb + (size_t)b * NC * NHW) + (size_t)z * CPZ * NG4;
    const float4* i4 = (const float4*)(ir  + (size_t)b * NC * NHW) + (size_t)z * CPZ * NG4;

    float4 s  = make_float4(0.f, 0.f, 0.f, 0.f);
    float4 mr = make_float4(-3.402823466e38f, -3.402823466e38f, -3.402823466e38f, -3.402823466e38f);
    float4 mi = mr;

    #pragma unroll 8
    for (int c = 0; c < CPZ; c++) {
        float4 a = __ldcs(r4 + c * NG4 + g);
        float4 d = __ldcs(i4 + c * NG4 + g);
        s.x += a.x + d.x; s.y += a.y + d.y; s.z += a.z + d.z; s.w += a.w + d.w;
        mr.x = fmaxf(mr.x, a.x); mr.y = fmaxf(mr.y, a.y);
        mr.z = fmaxf(mr.z, a.z); mr.w = fmaxf(mr.w, a.w);
        mi.x = fmaxf(mi.x, d.x); mi.y = fmaxf(mi.y, d.y);
        mi.z = fmaxf(mi.z, d.z); mi.w = fmaxf(mi.w, d.w);
    }
    size_t o = ((size_t)z * NB + b) * NG4 + g;
    g_ps[o] = s; g_pmr[o] = mr; g_pmi[o] = mi;   // default policy: L2-resident
}

// ---------------------------------------------------------------------------
// Pass 1b: combine 8 partials -> sa = max(mean, max_r + max_i) -> sigmoid.
// ---------------------------------------------------------------------------
__global__ void __launch_bounds__(128) k_sa2() {
    int g = blockIdx.x * blockDim.x + threadIdx.x;
    if (g >= NG4) return;
    int b = blockIdx.y;

    float4 s  = make_float4(0.f, 0.f, 0.f, 0.f);
    float4 mr = make_float4(-3.402823466e38f, -3.402823466e38f, -3.402823466e38f, -3.402823466e38f);
    float4 mi = mr;

    #pragma unroll
    for (int z = 0; z < NZ; z++) {
        size_t o = ((size_t)z * NB + b) * NG4 + g;
        float4 ps = g_ps[o], pr = g_pmr[o], pi = g_pmi[o];
        s.x += ps.x; s.y += ps.y; s.z += ps.z; s.w += ps.w;
        mr.x = fmaxf(mr.x, pr.x); mr.y = fmaxf(mr.y, pr.y);
        mr.z = fmaxf(mr.z, pr.z); mr.w = fmaxf(mr.w, pr.w);
        mi.x = fmaxf(mi.x, pi.x); mi.y = fmaxf(mi.y, pi.y);
        mi.z = fmaxf(mi.z, pi.z); mi.w = fmaxf(mi.w, pi.w);
    }
    const float invC = 1.0f / (float)NC;
    float4 o4;
    float sa;
    sa = fmaxf(s.x * invC, mr.x + mi.x); o4.x = 1.0f / (1.0f + expf(-sa));
    sa = fmaxf(s.y * invC, mr.y + mi.y); o4.y = 1.0f / (1.0f + expf(-sa));
    sa = fmaxf(s.z * invC, mr.z + mi.z); o4.z = 1.0f / (1.0f + expf(-sa));
    sa = fmaxf(s.w * invC, mr.w + mi.w); o4.w = 1.0f / (1.0f + expf(-sa));
    ((float4*)(g_sa + (size_t)b * NHW))[g] = o4;
}

// ---------------------------------------------------------------------------
// Pass 2: 8 channels per block — one sa load feeds 8 dot accumulations
// (sa L2 traffic /8); 8 independent streaming loads per iteration for MLP.
// ---------------------------------------------------------------------------
__global__ void __launch_bounds__(128) k_stats(const float* __restrict__ rgb,
                                               const float* __restrict__ ir) {
    int c0 = blockIdx.x * 8, b = blockIdx.y, s = blockIdx.z;
    int tid = threadIdx.x;

    const float4* x4  = (const float4*)((s == 0 ? rgb : ir) + ((size_t)b * NC + c0) * NHW);
    const float4* sa4 = (const float4*)(g_sa + (size_t)b * NHW);

    float d[8], n[8];
    #pragma unroll
    for (int k = 0; k < 8; k++) { d[k] = 0.f; n[k] = 0.f; }

    for (int g = tid; g < NG4; g += 128) {
        float4 a = sa4[g];
        #pragma unroll
        for (int k = 0; k < 8; k++) {
            float4 v = __ldcs(x4 + k * NG4 + g);
            d[k] += v.x * a.x + v.y * a.y + v.z * a.z + v.w * a.w;
            n[k] += v.x * v.x + v.y * v.y + v.z * v.z + v.w * v.w;
        }
    }
    #pragma unroll
    for (int o = 16; o > 0; o >>= 1) {
        #pragma unroll
        for (int k = 0; k < 8; k++) {
            d[k] += __shfl_down_sync(0xffffffffu, d[k], o);
            n[k] += __shfl_down_sync(0xffffffffu, n[k], o);
        }
    }
    __shared__ float sd[4][8], sn[4][8];   // [warp][channel]
    if ((tid & 31) == 0) {
        int w = tid >> 5;
        #pragma unroll
        for (int k = 0; k < 8; k++) { sd[w][k] = d[k]; sn[w][k] = n[k]; }
    }
    __syncthreads();
    if (tid < 8) {
        float dd = (sd[0][tid] + sd[1][tid]) + (sd[2][tid] + sd[3][tid]);
        float nn = (sn[0][tid] + sn[1][tid]) + (sn[2][tid] + sn[3][tid]);
        g_dot[s][b * NC + c0 + tid] = dd;
        g_nsq[s][b * NC + c0 + tid] = nn;
    }
}

// ---------------------------------------------------------------------------
// Pass 3: ordering key = dot / nx (common positive factor ||sa|| dropped:
// identical argsort order and sign). Positive count -> atomicMax(g_n[s]);
// stable rank argsort via broadcast LDS.128 loop.
// ---------------------------------------------------------------------------
__global__ void __launch_bounds__(256) k_sort() {
    int b = blockIdx.x, s = blockIdx.y;
    int tid = threadIdx.x;  // 256 == NC

    __shared__ __align__(16) float s_key[NC];

    float nx  = fmaxf(sqrtf(g_nsq[s][b * NC + tid]), EPSF);
    float sim = g_dot[s][b * NC + tid] / nx;
    s_key[tid] = sim;

    int cnt = __syncthreads_count(sim > 0.f);   // barrier also publishes s_key
    if (tid == 0) atomicMax(&g_n[s], cnt);      // batch max (reset in k_sa1)

    // stable rank: # keys strictly less, plus equal keys with smaller index
    const float4* k4 = (const float4*)s_key;
    int rank = 0;
    #pragma unroll 8
    for (int j4 = 0; j4 < NC / 4; j4++) {
        float4 k = k4[j4];                       // broadcast LDS.128
        int j = j4 * 4;
        rank += (k.x < sim) || (k.x == sim && j     < tid);
        rank += (k.y < sim) || (k.y == sim && j + 1 < tid);
        rank += (k.z < sim) || (k.z == sim && j + 2 < tid);
        rank += (k.w < sim) || (k.w == sim && j + 3 < tid);
    }
    g_ord[s][b * NC + rank] = tid;               // channel tid sits at position rank
}

// ---------------------------------------------------------------------------
// Pass 4: out = (src>=0 ? x[src] : max(rgb[lo0], ir[lo1])) * sa_sig.
// 4 channels per thread (same b,g): one sa load + one metadata set feeds
// 8 gathers/8 stores. srcmap derived inline from g_ord + g_n. Warp-uniform
// channel indices keep every gather coalesced.
// ---------------------------------------------------------------------------
__device__ __forceinline__ int src_of(const int* __restrict__ ord, int c,
                                      int n_self, int n_other) {
    if (n_other > n_self && n_self < NC) {
        if (c < n_self)  return __ldg(ord + c);
        if (c == n_self) return -1;              // extra_fea slot
        return __ldg(ord + c - 1);
    }
    return __ldg(ord + c);
}

__global__ void __launch_bounds__(256) k_out(const float* __restrict__ rgb,
                                             const float* __restrict__ ir,
                                             float* __restrict__ out) {
    int idx = blockIdx.x * blockDim.x + threadIdx.x;     // [0, NB*64*NG4)
    int g  = idx % NG4;
    int t  = idx / NG4;
    int cp = t & 63;
    int b  = t >> 6;
    int c0 = cp * 4;

    float4 a = __ldg((const float4*)(g_sa + (size_t)b * NHW) + g);

    const float4* rb = (const float4*)(rgb + (size_t)b * NC * NHW);
    const float4* ib = (const float4*)(ir  + (size_t)b * NC * NHW);

    int n0 = __ldg(&g_n[0]);
    int n1 = __ldg(&g_n[1]);
    const int* ord0 = g_ord[0] + b * NC;
    const int* ord1 = g_ord[1] + b * NC;

    int sr[4], si[4];
    #pragma unroll
    for (int k = 0; k < 4; k++) {
        sr[k] = src_of(ord0, c0 + k, n0, n1);
        si[k] = src_of(ord1, c0 + k, n1, n0);
    }

    float4 ex;  // extra_fea = max(lowest-sim rgb, lowest-sim ir); lazy
    bool need_ex = false;
    #pragma unroll
    for (int k = 0; k < 4; k++) need_ex |= (sr[k] < 0) | (si[k] < 0);
    if (need_ex) {
        float4 p = __ldcs(rb + (size_t)__ldg(ord0) * NG4 + g);
        float4 q = __ldcs(ib + (size_t)__ldg(ord1) * NG4 + g);
        ex = make_float4(fmaxf(p.x, q.x), fmaxf(p.y, q.y), fmaxf(p.z, q.z), fmaxf(p.w, q.w));
    }

    float4 vr[4], vi[4];
    #pragma unroll
    for (int k = 0; k < 4; k++)
        vr[k] = (sr[k] >= 0) ? __ldcs(rb + (size_t)sr[k] * NG4 + g) : ex;
    #pragma unroll
    for (int k = 0; k < 4; k++)
        vi[k] = (si[k] >= 0) ? __ldcs(ib + (size_t)si[k] * NG4 + g) : ex;

    size_t base_r = ((size_t)b * NC + c0) * NG4 + g;
    size_t base_i = (size_t)NB * NC * NG4 + base_r;

    #pragma unroll
    for (int k = 0; k < 4; k++)
        __stcs((float4*)out + base_r + (size_t)k * NG4,
               make_float4(vr[k].x * a.x, vr[k].y * a.y, vr[k].z * a.z, vr[k].w * a.w));
    #pragma unroll
    for (int k = 0; k < 4; k++)
        __stcs((float4*)out + base_i + (size_t)k * NG4,
               make_float4(vi[k].x * a.x, vi[k].y * a.y, vi[k].z * a.z, vi[k].w * a.w));
}

extern "C" void kernel_launch(void* const* d_in, const int* in_sizes, int n_in,
                              void* d_out, int out_size) {
    (void)in_sizes; (void)n_in; (void)out_size;
    const float* rgb = (const float*)d_in[0];
    const float* ir  = (const float*)d_in[1];
    float* out = (float*)d_out;

    k_sa1<<<dim3(7, NB, NZ), 128>>>(rgb, ir);
    k_sa2<<<dim3(7, NB), 128>>>();
    k_stats<<<dim3(NC / 8, NB, 2), 128>>>(rgb, ir);
    k_sort<<<dim3(NB, 2), 256>>>();
    k_out<<<(NB * 64 * NG4) / 256, 256>>>(rgb, ir, out);
}

// round 17
// speedup vs baseline: 1.1859x; 1.0198x over previous
#include <cuda_runtime.h>
#include <math.h>

// CSCR fused pipeline, B=32, C=256, H=W=56 (HW=3136), sm_103a.
// R11 5-kernel structure (measured 142.1/143.4 us) + PDL (griddepcontrol)
// on every graph edge to hide inter-node launch latency.
// k_sa1: partial channel reduce (C split x8) + g_n reset  [reads 205.5 MB, streaming]
// k_sa2: combine partials -> sigmoid(sa)                   [reads 9.6 MB, L2-resident]
// k_stats: 8-ch blocks: dot(sa,x), ||x||^2                 [reads 205.5 MB, streaming]
// k_sort: key = dot/nx, positive counts -> atomicMax(g_n), stable rank argsort
// k_out: 4-ch/thread inline srcmap gather * sa             [reads 205.5, writes 205.5 MB]

#define NB  32
#define NC  256
#define NHW 3136
#define NG4 784            // NHW/4
#define NZ  8              // C-chunks in k_sa1
#define CPZ 32             // channels per chunk
#define EPSF 1e-12f

__device__ __forceinline__ void gdc_wait()   { asm volatile("griddepcontrol.wait;" ::: "memory"); }
__device__ __forceinline__ void gdc_launch() { asm volatile("griddepcontrol.launch_dependents;" ::: "memory"); }

__device__ __align__(16) float  g_sa[NB * NHW];        // sigmoid(sa)
__device__ __align__(16) float4 g_ps [NZ * NB * NG4];  // partial sum (rgb+ir combined)
__device__ __align__(16) float4 g_pmr[NZ * NB * NG4];  // partial max rgb
__device__ __align__(16) float4 g_pmi[NZ * NB * NG4];  // partial max ir
__device__ float g_dot[2][NB * NC];
__device__ float g_nsq[2][NB * NC];
__device__ int   g_ord[2][NB * NC];
__device__ int   g_n[2];

// ---------------------------------------------------------------------------
// Pass 1a: partial per-pixel channel reductions over a 32-channel chunk.
// grid (7, B, 8) x 128. Streaming loads. Block (0,0,0) also resets g_n.
// ---------------------------------------------------------------------------
__global__ void __launch_bounds__(128) k_sa1(const float* __restrict__ rgb,
                                             const float* __restrict__ ir) {
    if (blockIdx.x == 0 && blockIdx.y == 0 && blockIdx.z == 0 && threadIdx.x < 2)
        g_n[threadIdx.x] = 0;

    int g = blockIdx.x * blockDim.x + threadIdx.x;
    if (g >= NG4) return;                        // exited threads count as PDL-triggered
    int b = blockIdx.y, z = blockIdx.z;

    const float4* r4 = (const float4*)(rgb + (size_t)b * NC * NHW) + (size_t)z * CPZ * NG4;
    const float4* i4 = (const float4*)(ir  + (size_t)b * NC * NHW) + (size_t)z * CPZ * NG4;

    float4 s  = make_float4(0.f, 0.f, 0.f, 0.f);
    float4 mr = make_float4(-3.402823466e38f, -3.402823466e38f, -3.402823466e38f, -3.402823466e38f);
    float4 mi = mr;

    #pragma unroll 8
    for (int c = 0; c < CPZ; c++) {
        float4 a = __ldcs(r4 + c * NG4 + g);
        float4 d = __ldcs(i4 + c * NG4 + g);
        s.x += a.x + d.x; s.y += a.y + d.y; s.z += a.z + d.z; s.w += a.w + d.w;
        mr.x = fmaxf(mr.x, a.x); mr.y = fmaxf(mr.y, a.y);
        mr.z = fmaxf(mr.z, a.z); mr.w = fmaxf(mr.w, a.w);
        mi.x = fmaxf(mi.x, d.x); mi.y = fmaxf(mi.y, d.y);
        mi.z = fmaxf(mi.z, d.z); mi.w = fmaxf(mi.w, d.w);
    }
    size_t o = ((size_t)z * NB + b) * NG4 + g;
    g_ps[o] = s; g_pmr[o] = mr; g_pmi[o] = mi;   // default policy: L2-resident
    gdc_launch();                                // stores done -> dependents may launch
}

// ---------------------------------------------------------------------------
// Pass 1b: combine 8 partials -> sa = max(mean, max_r + max_i) -> sigmoid.
// ---------------------------------------------------------------------------
__global__ void __launch_bounds__(128) k_sa2() {
    gdc_wait();                                  // acquire k_sa1's partial stores
    int g = blockIdx.x * blockDim.x + threadIdx.x;
    if (g >= NG4) return;
    int b = blockIdx.y;

    float4 s  = make_float4(0.f, 0.f, 0.f, 0.f);
    float4 mr = make_float4(-3.402823466e38f, -3.402823466e38f, -3.402823466e38f, -3.402823466e38f);
    float4 mi = mr;

    #pragma unroll
    for (int z = 0; z < NZ; z++) {
        size_t o = ((size_t)z * NB + b) * NG4 + g;
        float4 ps = g_ps[o], pr = g_pmr[o], pi = g_pmi[o];
        s.x += ps.x; s.y += ps.y; s.z += ps.z; s.w += ps.w;
        mr.x = fmaxf(mr.x, pr.x); mr.y = fmaxf(mr.y, pr.y);
        mr.z = fmaxf(mr.z, pr.z); mr.w = fmaxf(mr.w, pr.w);
        mi.x = fmaxf(mi.x, pi.x); mi.y = fmaxf(mi.y, pi.y);
        mi.z = fmaxf(mi.z, pi.z); mi.w = fmaxf(mi.w, pi.w);
    }
    const float invC = 1.0f / (float)NC;
    float4 o4;
    float sa;
    sa = fmaxf(s.x * invC, mr.x + mi.x); o4.x = 1.0f / (1.0f + expf(-sa));
    sa = fmaxf(s.y * invC, mr.y + mi.y); o4.y = 1.0f / (1.0f + expf(-sa));
    sa = fmaxf(s.z * invC, mr.z + mi.z); o4.z = 1.0f / (1.0f + expf(-sa));
    sa = fmaxf(s.w * invC, mr.w + mi.w); o4.w = 1.0f / (1.0f + expf(-sa));
    ((float4*)(g_sa + (size_t)b * NHW))[g] = o4;
    gdc_launch();
}

// ---------------------------------------------------------------------------
// Pass 2: 8 channels per block — one sa load feeds 8 dot accumulations
// (sa L2 traffic /8); 8 independent streaming loads per iteration for MLP.
// ---------------------------------------------------------------------------
__global__ void __launch_bounds__(128) k_stats(const float* __restrict__ rgb,
                                               const float* __restrict__ ir) {
    gdc_wait();                                  // acquire g_sa
    int c0 = blockIdx.x * 8, b = blockIdx.y, s = blockIdx.z;
    int tid = threadIdx.x;

    const float4* x4  = (const float4*)((s == 0 ? rgb : ir) + ((size_t)b * NC + c0) * NHW);
    const float4* sa4 = (const float4*)(g_sa + (size_t)b * NHW);

    float d[8], n[8];
    #pragma unroll
    for (int k = 0; k < 8; k++) { d[k] = 0.f; n[k] = 0.f; }

    for (int g = tid; g < NG4; g += 128) {
        float4 a = sa4[g];
        #pragma unroll
        for (int k = 0; k < 8; k++) {
            float4 v = __ldcs(x4 + k * NG4 + g);
            d[k] += v.x * a.x + v.y * a.y + v.z * a.z + v.w * a.w;
            n[k] += v.x * v.x + v.y * v.y + v.z * v.z + v.w * v.w;
        }
    }
    #pragma unroll
    for (int o = 16; o > 0; o >>= 1) {
        #pragma unroll
        for (int k = 0; k < 8; k++) {
            d[k] += __shfl_down_sync(0xffffffffu, d[k], o);
            n[k] += __shfl_down_sync(0xffffffffu, n[k], o);
        }
    }
    __shared__ float sd[4][8], sn[4][8];   // [warp][channel]
    if ((tid & 31) == 0) {
        int w = tid >> 5;
        #pragma unroll
        for (int k = 0; k < 8; k++) { sd[w][k] = d[k]; sn[w][k] = n[k]; }
    }
    __syncthreads();
    if (tid < 8) {
        float dd = (sd[0][tid] + sd[1][tid]) + (sd[2][tid] + sd[3][tid]);
        float nn = (sn[0][tid] + sn[1][tid]) + (sn[2][tid] + sn[3][tid]);
        g_dot[s][b * NC + c0 + tid] = dd;
        g_nsq[s][b * NC + c0 + tid] = nn;
    }
    gdc_launch();
}

// ---------------------------------------------------------------------------
// Pass 3: ordering key = dot / nx (common positive factor ||sa|| dropped:
// identical argsort order and sign). Positive count -> atomicMax(g_n[s]);
// stable rank argsort via broadcast LDS.128 loop.
// ---------------------------------------------------------------------------
__global__ void __launch_bounds__(256) k_sort() {
    gdc_wait();                                  // acquire g_dot/g_nsq
    int b = blockIdx.x, s = blockIdx.y;
    int tid = threadIdx.x;  // 256 == NC

    __shared__ __align__(16) float s_key[NC];

    float nx  = fmaxf(sqrtf(g_nsq[s][b * NC + tid]), EPSF);
    float sim = g_dot[s][b * NC + tid] / nx;
    s_key[tid] = sim;

    int cnt = __syncthreads_count(sim > 0.f);   // barrier also publishes s_key
    if (tid == 0) atomicMax(&g_n[s], cnt);      // batch max (reset in k_sa1)

    // stable rank: # keys strictly less, plus equal keys with smaller index
    const float4* k4 = (const float4*)s_key;
    int rank = 0;
    #pragma unroll 8
    for (int j4 = 0; j4 < NC / 4; j4++) {
        float4 k = k4[j4];                       // broadcast LDS.128
        int j = j4 * 4;
        rank += (k.x < sim) || (k.x == sim && j     < tid);
        rank += (k.y < sim) || (k.y == sim && j + 1 < tid);
        rank += (k.z < sim) || (k.z == sim && j + 2 < tid);
        rank += (k.w < sim) || (k.w == sim && j + 3 < tid);
    }
    g_ord[s][b * NC + rank] = tid;               // channel tid sits at position rank
    gdc_launch();
}

// ---------------------------------------------------------------------------
// Pass 4: out = (src>=0 ? x[src] : max(rgb[lo0], ir[lo1])) * sa_sig.
// 4 channels per thread; srcmap derived inline from g_ord + g_n.
// gdc_wait FIRST: even g_sa's visibility flows through the PDL chain.
// ---------------------------------------------------------------------------
__device__ __forceinline__ int src_of(const int* __restrict__ ord, int c,
                                      int n_self, int n_other) {
    if (n_other > n_self && n_self < NC) {
        if (c < n_self)  return __ldg(ord + c);
        if (c == n_self) return -1;              // extra_fea slot
        return __ldg(ord + c - 1);
    }
    return __ldg(ord + c);
}

__global__ void __launch_bounds__(256) k_out(const float* __restrict__ rgb,
                                             const float* __restrict__ ir,
                                             float* __restrict__ out) {
    gdc_wait();                                  // acquire g_ord/g_n (+chain: g_sa)
    int idx = blockIdx.x * blockDim.x + threadIdx.x;     // [0, NB*64*NG4)
    int g  = idx % NG4;
    int t  = idx / NG4;
    int cp = t & 63;
    int b  = t >> 6;
    int c0 = cp * 4;

    float4 a = __ldg((const float4*)(g_sa + (size_t)b * NHW) + g);

    const float4* rb = (const float4*)(rgb + (size_t)b * NC * NHW);
    const float4* ib = (const float4*)(ir  + (size_t)b * NC * NHW);

    int n0 = __ldg(&g_n[0]);
    int n1 = __ldg(&g_n[1]);
    const int* ord0 = g_ord[0] + b * NC;
    const int* ord1 = g_ord[1] + b * NC;

    int sr[4], si[4];
    #pragma unroll
    for (int k = 0; k < 4; k++) {
        sr[k] = src_of(ord0, c0 + k, n0, n1);
        si[k] = src_of(ord1, c0 + k, n1, n0);
    }

    float4 ex;  // extra_fea = max(lowest-sim rgb, lowest-sim ir); lazy
    bool need_ex = false;
    #pragma unroll
    for (int k = 0; k < 4; k++) need_ex |= (sr[k] < 0) | (si[k] < 0);
    if (need_ex) {
        float4 p = __ldcs(rb + (size_t)__ldg(ord0) * NG4 + g);
        float4 q = __ldcs(ib + (size_t)__ldg(ord1) * NG4 + g);
        ex = make_float4(fmaxf(p.x, q.x), fmaxf(p.y, q.y), fmaxf(p.z, q.z), fmaxf(p.w, q.w));
    }

    float4 vr[4], vi[4];
    #pragma unroll
    for (int k = 0; k < 4; k++)
        vr[k] = (sr[k] >= 0) ? __ldcs(rb + (size_t)sr[k] * NG4 + g) : ex;
    #pragma unroll
    for (int k = 0; k < 4; k++)
        vi[k] = (si[k] >= 0) ? __ldcs(ib + (size_t)si[k] * NG4 + g) : ex;

    size_t base_r = ((size_t)b * NC + c0) * NG4 + g;
    size_t base_i = (size_t)NB * NC * NG4 + base_r;

    #pragma unroll
    for (int k = 0; k < 4; k++)
        __stcs((float4*)out + base_r + (size_t)k * NG4,
               make_float4(vr[k].x * a.x, vr[k].y * a.y, vr[k].z * a.z, vr[k].w * a.w));
    #pragma unroll
    for (int k = 0; k < 4; k++)
        __stcs((float4*)out + base_i + (size_t)k * NG4,
               make_float4(vi[k].x * a.x, vi[k].y * a.y, vi[k].z * a.z, vi[k].w * a.w));
}

// ---------------------------------------------------------------------------
// Host: launch with programmatic stream serialization so each dependent grid
// is initialized while its predecessor drains (PDL graph edges).
// ---------------------------------------------------------------------------
template <typename K, typename... Args>
static inline void launch_pdl(dim3 grid, dim3 block, K kernel, Args... args) {
    cudaLaunchConfig_t cfg = {};
    cfg.gridDim = grid;
    cfg.blockDim = block;
    cfg.dynamicSmemBytes = 0;
    cfg.stream = 0;
    cudaLaunchAttribute attr[1];
    attr[0].id = cudaLaunchAttributeProgrammaticStreamSerialization;
    attr[0].val.programmaticStreamSerializationAllowed = 1;
    cfg.attrs = attr;
    cfg.numAttrs = 1;
    cudaLaunchKernelEx(&cfg, kernel, args...);
}

extern "C" void kernel_launch(void* const* d_in, const int* in_sizes, int n_in,
                              void* d_out, int out_size) {
    (void)in_sizes; (void)n_in; (void)out_size;
    const float* rgb = (const float*)d_in[0];
    const float* ir  = (const float*)d_in[1];
    float* out = (float*)d_out;

    k_sa1<<<dim3(7, NB, NZ), 128>>>(rgb, ir);
    launch_pdl(dim3(7, NB), dim3(128), k_sa2);
    launch_pdl(dim3(NC / 8, NB, 2), dim3(128), k_stats, rgb, ir);
    launch_pdl(dim3(NB, 2), dim3(256), k_sort);
    launch_pdl(dim3((NB * 64 * NG4) / 256), dim3(256), k_out, rgb, ir, out);
}